// round 16
// baseline (speedup 1.0000x reference)
#include <cuda_runtime.h>
#include <cuda_bf16.h>
#include <cuda_fp16.h>
#include <cstdint>

#define N_NODES 50000
#define N_EDGES 800000
#define NFEAT   128
#define DEG_CAP 96
#define BM      64      // GEMM rows per block
#define ASU     68      // As plane stride in uints -> ldmatrix phases conflict-free
#define WSU     36      // W plane stride in uints  -> ldmatrix phases conflict-free
#define GEMM_BLOCKS ((N_NODES + BM - 1) / BM)        // 782
#define FILL_BLOCKS 782                               // 782*256*4 >= N_EDGES

// Device-global scratch (allocation forbidden). Zero-initialized at load.
// g_cnt invariant: zero on entry to every kernel_launch call (gather kernel
// re-zeroes each node's counter after consuming it).
__device__ int g_cnt[N_NODES];
__device__ int g_bin[(size_t)N_NODES * DEG_CAP];
__device__ unsigned g_wbh[NFEAT * NFEAT / 2];   // W bf16-hi, packed k-pairs, n-major [128][64]
__device__ unsigned g_wbl[NFEAT * NFEAT / 2];   // W bf16-lo
__device__ __align__(16) unsigned g_y[(size_t)N_NODES * 64];  // Y fp16 pairs [N][64]

// ---------------------------------------------------------------------------
// bf16 helpers
// ---------------------------------------------------------------------------
__device__ __forceinline__ void bf16_split_pack(float x0, float x1,
                                                unsigned& hi, unsigned& lo) {
    __nv_bfloat16 h0 = __float2bfloat16(x0);
    __nv_bfloat16 h1 = __float2bfloat16(x1);
    float r0 = x0 - __bfloat162float(h0);
    float r1 = x1 - __bfloat162float(h1);
    __nv_bfloat16 l0 = __float2bfloat16(r0);
    __nv_bfloat16 l1 = __float2bfloat16(r1);
    unsigned uh0 = *reinterpret_cast<unsigned short*>(&h0);
    unsigned uh1 = *reinterpret_cast<unsigned short*>(&h1);
    unsigned ul0 = *reinterpret_cast<unsigned short*>(&l0);
    unsigned ul1 = *reinterpret_cast<unsigned short*>(&l1);
    hi = uh0 | (uh1 << 16);
    lo = ul0 | (ul1 << 16);
}

__device__ __forceinline__ void mma_bf16(float* c, const unsigned* a, const unsigned* b) {
    asm("mma.sync.aligned.m16n8k16.row.col.f32.bf16.bf16.f32 "
        "{%0,%1,%2,%3}, {%4,%5,%6,%7}, {%8,%9}, {%0,%1,%2,%3};"
        : "+f"(c[0]), "+f"(c[1]), "+f"(c[2]), "+f"(c[3])
        : "r"(a[0]), "r"(a[1]), "r"(a[2]), "r"(a[3]), "r"(b[0]), "r"(b[1]));
}

__device__ __forceinline__ void ldmatrix_x4(unsigned* r, uint32_t saddr) {
    asm volatile("ldmatrix.sync.aligned.m8n8.x4.shared.b16 {%0,%1,%2,%3}, [%4];"
                 : "=r"(r[0]), "=r"(r[1]), "=r"(r[2]), "=r"(r[3]) : "r"(saddr));
}

// ---------------------------------------------------------------------------
// Kernel 1: W bf16 hi/lo split (8192 threads, ~3us).
// ---------------------------------------------------------------------------
__global__ void splitw_kernel(const float* __restrict__ Wm) {
    int gid = blockIdx.x * blockDim.x + threadIdx.x;
    int n  = gid >> 6;
    int kq = gid & 63;
    float2 w = *reinterpret_cast<const float2*>(Wm + n * NFEAT + kq * 2);
    unsigned hu, lu;
    bf16_split_pack(w.x, w.y, hu, lu);
    g_wbh[n * 64 + kq] = hu;
    g_wbl[n * 64 + kq] = lu;
}

// ---------------------------------------------------------------------------
// Kernel 2: block-specialized matmul + edge-fill, interleaved even/odd.
// Even blocks: Y-tile = feature-tile @ W^T (3-pass bf16 m16n8k16, ldmatrix).
// Odd blocks: binned edge fill (4 edges/thread, int4 loads + ATOMG bumps).
// The fill uses ONLY the L2 atomic ALUs; the matmul uses tensor/LSU/smem —
// co-resident blocks overlap the two resource classes, collapsing the
// previous prep+matmul serialization (31.6us) toward max(15, 16).
// ---------------------------------------------------------------------------
__global__ __launch_bounds__(256, 3)
void matmul_fill_kernel(const float* __restrict__ feature,
                        const int*   __restrict__ src,
                        const int*   __restrict__ dst) {
    // ---- Odd blocks: edge fill, no smem, no barriers ----
    if (blockIdx.x & 1) {
        int fb  = blockIdx.x >> 1;                      // 0..781
        int gid = fb * 256 + threadIdx.x;               // int4 group id
        if (gid < N_EDGES / 4) {
            int4 d4 = reinterpret_cast<const int4*>(dst)[gid];
            int4 s4 = reinterpret_cast<const int4*>(src)[gid];
            int p;
            p = atomicAdd(&g_cnt[d4.x], 1); if (p < DEG_CAP) g_bin[(size_t)d4.x * DEG_CAP + p] = s4.x;
            p = atomicAdd(&g_cnt[d4.y], 1); if (p < DEG_CAP) g_bin[(size_t)d4.y * DEG_CAP + p] = s4.y;
            p = atomicAdd(&g_cnt[d4.z], 1); if (p < DEG_CAP) g_bin[(size_t)d4.z * DEG_CAP + p] = s4.z;
            p = atomicAdd(&g_cnt[d4.w], 1); if (p < DEG_CAP) g_bin[(size_t)d4.w * DEG_CAP + p] = s4.w;
        }
        return;
    }

    // ---- Even blocks: GEMM tile ----
    extern __shared__ unsigned usm[];
    unsigned* ash = usm;                 // [64][ASU] bf16-hi k-pairs
    unsigned* asl = ash + BM * ASU;      // [64][ASU] bf16-lo
    unsigned* wh  = asl + BM * ASU;      // [128][WSU] W-hi tile (k64)
    unsigned* wl  = wh + 128 * WSU;      // [128][WSU] W-lo tile

    const int tid  = threadIdx.x;
    const int lane = tid & 31;
    const int warp = tid >> 5;
    const int block_m = (blockIdx.x >> 1) * BM;

    // ---- Stage As: read feature, split to bf16 hi/lo packed pairs ----
    #pragma unroll
    for (int i = 0; i < 16; i++) {
        int idx = tid + i * 256;         // 0..4095
        int row = idx >> 6;              // 0..63
        int kq  = idx & 63;              // pair index
        int grow = block_m + row;
        float x0 = 0.f, x1 = 0.f;
        if (grow < N_NODES) {
            float2 v = *reinterpret_cast<const float2*>(
                feature + (size_t)grow * NFEAT + kq * 2);
            x0 = v.x; x1 = v.y;
        }
        unsigned hu, lu;
        bf16_split_pack(x0, x1, hu, lu);
        ash[row * ASU + kq] = hu;
        asl[row * ASU + kq] = lu;
    }

    // ---- Stage W tile kb=0 (uint4 copies) ----
    #pragma unroll
    for (int i = 0; i < 4; i++) {
        int idx = tid + i * 256;         // 0..1023
        int n   = idx >> 3;              // 0..127
        int q   = idx & 7;               // uint4 index
        uint4 vh = *reinterpret_cast<const uint4*>(g_wbh + n * 64 + q * 4);
        *reinterpret_cast<uint4*>(wh + n * WSU + q * 4) = vh;
        uint4 vl = *reinterpret_cast<const uint4*>(g_wbl + n * 64 + q * 4);
        *reinterpret_cast<uint4*>(wl + n * WSU + q * 4) = vl;
    }

    const int wm = (warp >> 2) * 32;     // 0, 32
    const int wn = (warp & 3) * 32;      // 0, 32, 64, 96
    const int g  = lane >> 2;            // 0..7
    const int t4 = lane & 3;             // 0..3

    const int a_row = (lane & 7) + ((lane & 8) ? 8 : 0);
    const int a_kof = (lane & 16) ? 4 : 0;
    const int b_row = (lane & 7) + ((lane & 16) ? 8 : 0);
    const int b_kof = (lane & 8) ? 4 : 0;

    const uint32_t s_ash = (uint32_t)__cvta_generic_to_shared(ash);
    const uint32_t s_asl = (uint32_t)__cvta_generic_to_shared(asl);
    const uint32_t s_wh  = (uint32_t)__cvta_generic_to_shared(wh);
    const uint32_t s_wl  = (uint32_t)__cvta_generic_to_shared(wl);

    float acc[2][4][4];
    #pragma unroll
    for (int mt = 0; mt < 2; mt++)
        #pragma unroll
        for (int nt = 0; nt < 4; nt++)
            #pragma unroll
            for (int q = 0; q < 4; q++)
                acc[mt][nt][q] = 0.f;

    #pragma unroll 1
    for (int kb = 0; kb < 2; kb++) {
        __syncthreads();   // As + W tile kb ready

        #pragma unroll
        for (int kk = 0; kk < 4; kk++) {
            const int ku = kb * 32 + kk * 8;

            unsigned ahi[2][4], alo[2][4];
            #pragma unroll
            for (int mt = 0; mt < 2; mt++) {
                uint32_t aoff = ((wm + mt * 16 + a_row) * ASU + ku + a_kof) * 4u;
                ldmatrix_x4(ahi[mt], s_ash + aoff);
                ldmatrix_x4(alo[mt], s_asl + aoff);
            }

            unsigned bh[4][2], bl[4][2];
            #pragma unroll
            for (int h = 0; h < 2; h++) {
                uint32_t boff = ((wn + h * 16 + b_row) * WSU + kk * 8 + b_kof) * 4u;
                unsigned th[4], tl[4];
                ldmatrix_x4(th, s_wh + boff);
                ldmatrix_x4(tl, s_wl + boff);
                bh[2*h][0] = th[0]; bh[2*h][1] = th[1];
                bh[2*h+1][0] = th[2]; bh[2*h+1][1] = th[3];
                bl[2*h][0] = tl[0]; bl[2*h][1] = tl[1];
                bl[2*h+1][0] = tl[2]; bl[2*h+1][1] = tl[3];
            }

            #pragma unroll
            for (int nt = 0; nt < 4; nt++) {
                #pragma unroll
                for (int mt = 0; mt < 2; mt++) {
                    mma_bf16(acc[mt][nt], ahi[mt], bh[nt]);
                    mma_bf16(acc[mt][nt], ahi[mt], bl[nt]);
                    mma_bf16(acc[mt][nt], alo[mt], bh[nt]);
                }
            }
        }
        __syncthreads();

        if (kb == 0) {
            #pragma unroll
            for (int i = 0; i < 4; i++) {
                int idx = tid + i * 256;
                int n   = idx >> 3;
                int q   = idx & 7;
                uint4 vh = *reinterpret_cast<const uint4*>(g_wbh + n * 64 + 32 + q * 4);
                *reinterpret_cast<uint4*>(wh + n * WSU + q * 4) = vh;
                uint4 vl = *reinterpret_cast<const uint4*>(g_wbl + n * 64 + 32 + q * 4);
                *reinterpret_cast<uint4*>(wl + n * WSU + q * 4) = vl;
            }
        }
    }

    // ---- Epilogue: pack to fp16 pairs, store to g_y ----
    #pragma unroll
    for (int mt = 0; mt < 2; mt++) {
        int r0 = block_m + wm + mt * 16 + g;
        int r1 = r0 + 8;
        #pragma unroll
        for (int nt = 0; nt < 4; nt++) {
            int cq = (wn + nt * 8 + 2 * t4) >> 1;   // packed-pair column index
            if (r0 < N_NODES) {
                __half2 h = __floats2half2_rn(acc[mt][nt][0], acc[mt][nt][1]);
                g_y[(size_t)r0 * 64 + cq] = *reinterpret_cast<unsigned*>(&h);
            }
            if (r1 < N_NODES) {
                __half2 h = __floats2half2_rn(acc[mt][nt][2], acc[mt][nt][3]);
                g_y[(size_t)r1 * 64 + cq] = *reinterpret_cast<unsigned*>(&h);
            }
        }
    }
}

// ---------------------------------------------------------------------------
// Kernel 3: gather-out — one warp per node, occ 4.
// Lane l owns cols 4l..4l+3 (uint2 per edge, one LDG.64). Edge pairs summed
// with HADD2 then flushed to fp32 (one fp16 add per pair, +~3e-4 rel).
// ---------------------------------------------------------------------------
__global__ __launch_bounds__(256, 4)
void gather_out_kernel(const float* __restrict__ bias,
                       float* __restrict__ out) {
    const int node = (int)((blockIdx.x * (size_t)blockDim.x + threadIdx.x) >> 5);
    const int lane = threadIdx.x & 31;
    const unsigned FULL = 0xffffffffu;
    if (node >= N_NODES) return;

    int cnt = g_cnt[node];
    if (cnt > DEG_CAP) cnt = DEG_CAP;
    const int sidx = g_bin[(size_t)node * DEG_CAP + lane];
    const uint2* y2 = reinterpret_cast<const uint2*>(g_y) + lane;   // row stride 32

    float a0 = 0.f, a1 = 0.f, a2 = 0.f, a3 = 0.f;

    const int nb = (cnt < 32) ? cnt : 32;
    int e = 0;
    for (; e + 16 <= nb; e += 16) {
        uint2 u[16];
        #pragma unroll
        for (int j = 0; j < 16; j++) {
            int s = __shfl_sync(FULL, sidx, e + j);
            u[j] = y2[(size_t)s * 32];
        }
        #pragma unroll
        for (int j = 0; j < 16; j += 2) {
            __half2 ha = __hadd2(*reinterpret_cast<__half2*>(&u[j].x),
                                 *reinterpret_cast<__half2*>(&u[j + 1].x));
            __half2 hb = __hadd2(*reinterpret_cast<__half2*>(&u[j].y),
                                 *reinterpret_cast<__half2*>(&u[j + 1].y));
            float2 fa = __half22float2(ha);
            float2 fb = __half22float2(hb);
            a0 += fa.x; a1 += fa.y; a2 += fb.x; a3 += fb.y;
        }
    }
    for (; e + 2 <= nb; e += 2) {
        int s0 = __shfl_sync(FULL, sidx, e);
        int s1 = __shfl_sync(FULL, sidx, e + 1);
        uint2 u0 = y2[(size_t)s0 * 32];
        uint2 u1 = y2[(size_t)s1 * 32];
        __half2 ha = __hadd2(*reinterpret_cast<__half2*>(&u0.x),
                             *reinterpret_cast<__half2*>(&u1.x));
        __half2 hb = __hadd2(*reinterpret_cast<__half2*>(&u0.y),
                             *reinterpret_cast<__half2*>(&u1.y));
        float2 fa = __half22float2(ha);
        float2 fb = __half22float2(hb);
        a0 += fa.x; a1 += fa.y; a2 += fb.x; a3 += fb.y;
    }
    if (e < nb) {
        int s = __shfl_sync(FULL, sidx, e);
        uint2 u = y2[(size_t)s * 32];
        float2 fa = __half22float2(*reinterpret_cast<__half2*>(&u.x));
        float2 fb = __half22float2(*reinterpret_cast<__half2*>(&u.y));
        a0 += fa.x; a1 += fa.y; a2 += fb.x; a3 += fb.y;
    }
    // rare: degree > 32 (base+lane <= 95 < DEG_CAP so the load is in-bounds)
    for (int base = 32; base < cnt; base += 32) {
        int sx = g_bin[(size_t)node * DEG_CAP + base + lane];
        int nb2 = cnt - base; if (nb2 > 32) nb2 = 32;
        for (int e2 = 0; e2 < nb2; e2++) {
            int s = __shfl_sync(FULL, sx, e2);
            uint2 u = y2[(size_t)s * 32];
            float2 fa = __half22float2(*reinterpret_cast<__half2*>(&u.x));
            float2 fb = __half22float2(*reinterpret_cast<__half2*>(&u.y));
            a0 += fa.x; a1 += fa.y; a2 += fb.x; a3 += fb.y;
        }
    }

    float4 bv = *reinterpret_cast<const float4*>(bias + 4 * lane);
    float4 o;
    o.x = fmaxf(a0 + bv.x, 0.f);
    o.y = fmaxf(a1 + bv.y, 0.f);
    o.z = fmaxf(a2 + bv.z, 0.f);
    o.w = fmaxf(a3 + bv.w, 0.f);
    *reinterpret_cast<float4*>(out + (size_t)node * NFEAT + 4 * lane) = o;

    if (lane == 0) g_cnt[node] = 0;   // restore invariant for next replay
}

// ---------------------------------------------------------------------------
// kernel_launch
// Inputs: feature [N,128] f32, src_idx [E] i32, dst_idx [E] i32,
//         W [128,128] f32, b [128] f32.  Output: [N,128] f32.
// Pipeline: splitw; {Y = F@W^T || edge-fill} (block-specialized, overlapped);
//           out = relu(SegmentSum(Y) + b).
// ---------------------------------------------------------------------------
extern "C" void kernel_launch(void* const* d_in, const int* in_sizes, int n_in,
                              void* d_out, int out_size) {
    const float* feature = (const float*)d_in[0];
    const int*   src_idx = (const int*)d_in[1];
    const int*   dst_idx = (const int*)d_in[2];
    const float* Wm      = (const float*)d_in[3];
    const float* bias    = (const float*)d_in[4];
    float*       out     = (float*)d_out;

    const int SMEM_GEMM = (2 * BM * ASU + 2 * 128 * WSU) * 4;  // 71680 B
    cudaFuncSetAttribute(matmul_fill_kernel,
                         cudaFuncAttributeMaxDynamicSharedMemorySize, SMEM_GEMM);

    // 1) W bf16 split
    splitw_kernel<<<32, 256>>>(Wm);

    // 2) matmul + edge-fill, block-specialized (even=GEMM, odd=fill)
    matmul_fill_kernel<<<GEMM_BLOCKS + FILL_BLOCKS, 256, SMEM_GEMM>>>(
        feature, src_idx, dst_idx);

    // 3) gather + bias + relu (LDG.64, HADD2 pairs, fp32 accumulate)
    int gather_blocks = (N_NODES * 32 + 255) / 256;   // 6250
    gather_out_kernel<<<gather_blocks, 256>>>(bias, out);
}

// round 17
// speedup vs baseline: 1.0300x; 1.0300x over previous
#include <cuda_runtime.h>
#include <cuda_bf16.h>
#include <cuda_fp16.h>
#include <cstdint>

#define N_NODES 50000
#define N_EDGES 800000
#define NFEAT   128
#define DEG_CAP 96
#define BM      64      // GEMM rows per block
#define ASU     68      // As plane stride in uints -> ldmatrix phases conflict-free
#define WSU     36      // W plane stride in uints  -> ldmatrix phases conflict-free

// Device-global scratch (allocation forbidden). Zero-initialized at load.
// g_cnt invariant: zero on entry to every kernel_launch call (gather kernel
// re-zeroes each node's counter after consuming it).
__device__ int g_cnt[N_NODES];
__device__ int g_bin[(size_t)N_NODES * DEG_CAP];
__device__ unsigned g_wbh[NFEAT * NFEAT / 2];   // W bf16-hi, packed k-pairs, n-major [128][64]
__device__ unsigned g_wbl[NFEAT * NFEAT / 2];   // W bf16-lo
__device__ __align__(16) unsigned g_y[(size_t)N_NODES * 64];  // Y fp16 pairs [N][64]

// ---------------------------------------------------------------------------
// helpers
// ---------------------------------------------------------------------------
__device__ __forceinline__ void bf16_split_pack(float x0, float x1,
                                                unsigned& hi, unsigned& lo) {
    __nv_bfloat16 h0 = __float2bfloat16(x0);
    __nv_bfloat16 h1 = __float2bfloat16(x1);
    float r0 = x0 - __bfloat162float(h0);
    float r1 = x1 - __bfloat162float(h1);
    __nv_bfloat16 l0 = __float2bfloat16(r0);
    __nv_bfloat16 l1 = __float2bfloat16(r1);
    unsigned uh0 = *reinterpret_cast<unsigned short*>(&h0);
    unsigned uh1 = *reinterpret_cast<unsigned short*>(&h1);
    unsigned ul0 = *reinterpret_cast<unsigned short*>(&l0);
    unsigned ul1 = *reinterpret_cast<unsigned short*>(&l1);
    hi = uh0 | (uh1 << 16);
    lo = ul0 | (ul1 << 16);
}

__device__ __forceinline__ void mma_bf16(float* c, const unsigned* a, const unsigned* b) {
    asm("mma.sync.aligned.m16n8k16.row.col.f32.bf16.bf16.f32 "
        "{%0,%1,%2,%3}, {%4,%5,%6,%7}, {%8,%9}, {%0,%1,%2,%3};"
        : "+f"(c[0]), "+f"(c[1]), "+f"(c[2]), "+f"(c[3])
        : "r"(a[0]), "r"(a[1]), "r"(a[2]), "r"(a[3]), "r"(b[0]), "r"(b[1]));
}

__device__ __forceinline__ void ldmatrix_x4(unsigned* r, uint32_t saddr) {
    asm volatile("ldmatrix.sync.aligned.m8n8.x4.shared.b16 {%0,%1,%2,%3}, [%4];"
                 : "=r"(r[0]), "=r"(r[1]), "=r"(r[2]), "=r"(r[3]) : "r"(saddr));
}

__device__ __forceinline__ __half2 as_h2(unsigned u) {
    return *reinterpret_cast<__half2*>(&u);
}

// 8-edge batch: load then HADD2-pair reduce into fp32 accumulators.
__device__ __forceinline__ void batch8(const uint2* __restrict__ y2, int sidx, int e,
                                       float& a0, float& a1, float& a2, float& a3) {
    const unsigned FULL = 0xffffffffu;
    uint2 u[8];
    #pragma unroll
    for (int j = 0; j < 8; j++) {
        int s = __shfl_sync(FULL, sidx, e + j);
        u[j] = y2[(size_t)s * 32];
    }
    #pragma unroll
    for (int j = 0; j < 8; j += 2) {
        __half2 ha = __hadd2(as_h2(u[j].x), as_h2(u[j + 1].x));
        __half2 hb = __hadd2(as_h2(u[j].y), as_h2(u[j + 1].y));
        float2 fa = __half22float2(ha);
        float2 fb = __half22float2(hb);
        a0 += fa.x; a1 += fa.y; a2 += fb.x; a3 += fb.y;
    }
}

__device__ __forceinline__ void edge1(const uint2* __restrict__ y2, int sidx, int e,
                                      float& a0, float& a1, float& a2, float& a3) {
    const unsigned FULL = 0xffffffffu;
    int s = __shfl_sync(FULL, sidx, e);
    uint2 u = y2[(size_t)s * 32];
    float2 fa = __half22float2(as_h2(u.x));
    float2 fb = __half22float2(as_h2(u.y));
    a0 += fa.x; a1 += fa.y; a2 += fb.x; a3 += fb.y;
}

// ---------------------------------------------------------------------------
// Kernel 1: W bf16 hi/lo split (8192 threads).
// ---------------------------------------------------------------------------
__global__ void splitw_kernel(const float* __restrict__ Wm) {
    int gid = blockIdx.x * blockDim.x + threadIdx.x;
    int n  = gid >> 6;
    int kq = gid & 63;
    float2 w = *reinterpret_cast<const float2*>(Wm + n * NFEAT + kq * 2);
    unsigned hu, lu;
    bf16_split_pack(w.x, w.y, hu, lu);
    g_wbh[n * 64 + kq] = hu;
    g_wbl[n * 64 + kq] = lu;
}

// ---------------------------------------------------------------------------
// Kernel 2: binned edge fill, one edge per thread (L2 atomic-ALU floor).
// ---------------------------------------------------------------------------
__global__ void fill_kernel(const int* __restrict__ src,
                            const int* __restrict__ dst) {
    int gid = blockIdx.x * blockDim.x + threadIdx.x;
    if (gid < N_EDGES) {
        int d = dst[gid];
        int s = src[gid];
        int p = atomicAdd(&g_cnt[d], 1);
        if (p < DEG_CAP) g_bin[(size_t)d * DEG_CAP + p] = s;
    }
}

// ---------------------------------------------------------------------------
// Kernel 3: Y = feature @ W^T, 3-pass bf16 m16n8k16 MMA, ldmatrix frags.
// Output stored as packed fp16 pairs (g_y). Block = 64 rows, 256 thr, occ 3.
// ---------------------------------------------------------------------------
__global__ __launch_bounds__(256, 3)
void matmul_kernel(const float* __restrict__ feature) {
    extern __shared__ unsigned usm[];
    unsigned* ash = usm;                 // [64][ASU] bf16-hi k-pairs
    unsigned* asl = ash + BM * ASU;      // [64][ASU] bf16-lo
    unsigned* wh  = asl + BM * ASU;      // [128][WSU] W-hi tile (k64)
    unsigned* wl  = wh + 128 * WSU;      // [128][WSU] W-lo tile

    const int tid  = threadIdx.x;
    const int lane = tid & 31;
    const int warp = tid >> 5;
    const int block_m = blockIdx.x * BM;

    // ---- Stage As: read feature, split to bf16 hi/lo packed pairs ----
    #pragma unroll
    for (int i = 0; i < 16; i++) {
        int idx = tid + i * 256;
        int row = idx >> 6;
        int kq  = idx & 63;
        int grow = block_m + row;
        float x0 = 0.f, x1 = 0.f;
        if (grow < N_NODES) {
            float2 v = *reinterpret_cast<const float2*>(
                feature + (size_t)grow * NFEAT + kq * 2);
            x0 = v.x; x1 = v.y;
        }
        unsigned hu, lu;
        bf16_split_pack(x0, x1, hu, lu);
        ash[row * ASU + kq] = hu;
        asl[row * ASU + kq] = lu;
    }

    // ---- Stage W tile kb=0 ----
    #pragma unroll
    for (int i = 0; i < 4; i++) {
        int idx = tid + i * 256;
        int n   = idx >> 3;
        int q   = idx & 7;
        uint4 vh = *reinterpret_cast<const uint4*>(g_wbh + n * 64 + q * 4);
        *reinterpret_cast<uint4*>(wh + n * WSU + q * 4) = vh;
        uint4 vl = *reinterpret_cast<const uint4*>(g_wbl + n * 64 + q * 4);
        *reinterpret_cast<uint4*>(wl + n * WSU + q * 4) = vl;
    }

    const int wm = (warp >> 2) * 32;
    const int wn = (warp & 3) * 32;
    const int g  = lane >> 2;
    const int t4 = lane & 3;

    const int a_row = (lane & 7) + ((lane & 8) ? 8 : 0);
    const int a_kof = (lane & 16) ? 4 : 0;
    const int b_row = (lane & 7) + ((lane & 16) ? 8 : 0);
    const int b_kof = (lane & 8) ? 4 : 0;

    const uint32_t s_ash = (uint32_t)__cvta_generic_to_shared(ash);
    const uint32_t s_asl = (uint32_t)__cvta_generic_to_shared(asl);
    const uint32_t s_wh  = (uint32_t)__cvta_generic_to_shared(wh);
    const uint32_t s_wl  = (uint32_t)__cvta_generic_to_shared(wl);

    float acc[2][4][4];
    #pragma unroll
    for (int mt = 0; mt < 2; mt++)
        #pragma unroll
        for (int nt = 0; nt < 4; nt++)
            #pragma unroll
            for (int q = 0; q < 4; q++)
                acc[mt][nt][q] = 0.f;

    #pragma unroll 1
    for (int kb = 0; kb < 2; kb++) {
        __syncthreads();

        #pragma unroll
        for (int kk = 0; kk < 4; kk++) {
            const int ku = kb * 32 + kk * 8;

            unsigned ahi[2][4], alo[2][4];
            #pragma unroll
            for (int mt = 0; mt < 2; mt++) {
                uint32_t aoff = ((wm + mt * 16 + a_row) * ASU + ku + a_kof) * 4u;
                ldmatrix_x4(ahi[mt], s_ash + aoff);
                ldmatrix_x4(alo[mt], s_asl + aoff);
            }

            unsigned bh[4][2], bl[4][2];
            #pragma unroll
            for (int h = 0; h < 2; h++) {
                uint32_t boff = ((wn + h * 16 + b_row) * WSU + kk * 8 + b_kof) * 4u;
                unsigned th[4], tl[4];
                ldmatrix_x4(th, s_wh + boff);
                ldmatrix_x4(tl, s_wl + boff);
                bh[2*h][0] = th[0]; bh[2*h][1] = th[1];
                bh[2*h+1][0] = th[2]; bh[2*h+1][1] = th[3];
                bl[2*h][0] = tl[0]; bl[2*h][1] = tl[1];
                bl[2*h+1][0] = tl[2]; bl[2*h+1][1] = tl[3];
            }

            #pragma unroll
            for (int nt = 0; nt < 4; nt++) {
                #pragma unroll
                for (int mt = 0; mt < 2; mt++) {
                    mma_bf16(acc[mt][nt], ahi[mt], bh[nt]);
                    mma_bf16(acc[mt][nt], ahi[mt], bl[nt]);
                    mma_bf16(acc[mt][nt], alo[mt], bh[nt]);
                }
            }
        }
        __syncthreads();

        if (kb == 0) {
            #pragma unroll
            for (int i = 0; i < 4; i++) {
                int idx = tid + i * 256;
                int n   = idx >> 3;
                int q   = idx & 7;
                uint4 vh = *reinterpret_cast<const uint4*>(g_wbh + n * 64 + 32 + q * 4);
                *reinterpret_cast<uint4*>(wh + n * WSU + q * 4) = vh;
                uint4 vl = *reinterpret_cast<const uint4*>(g_wbl + n * 64 + 32 + q * 4);
                *reinterpret_cast<uint4*>(wl + n * WSU + q * 4) = vl;
            }
        }
    }

    // ---- Epilogue: pack to fp16 pairs, store to g_y ----
    #pragma unroll
    for (int mt = 0; mt < 2; mt++) {
        int r0 = block_m + wm + mt * 16 + g;
        int r1 = r0 + 8;
        #pragma unroll
        for (int nt = 0; nt < 4; nt++) {
            int cq = (wn + nt * 8 + 2 * t4) >> 1;
            if (r0 < N_NODES) {
                __half2 h = __floats2half2_rn(acc[mt][nt][0], acc[mt][nt][1]);
                g_y[(size_t)r0 * 64 + cq] = *reinterpret_cast<unsigned*>(&h);
            }
            if (r1 < N_NODES) {
                __half2 h = __floats2half2_rn(acc[mt][nt][2], acc[mt][nt][3]);
                g_y[(size_t)r1 * 64 + cq] = *reinterpret_cast<unsigned*>(&h);
            }
        }
    }
}

// ---------------------------------------------------------------------------
// Kernel 4: gather-out — TWO nodes per warp (independent edge streams give
// 2x ILP: common phase issues 8+8 loads from two shfl chains before any
// reduction). Lane l owns cols 4l..4l+3 (one LDG.64/edge). HADD2 pair
// reduction (one fp16 add per pair). occ 3 so the 32-reg batch stays
// register-resident.
// ---------------------------------------------------------------------------
__global__ __launch_bounds__(256, 3)
void gather_out_kernel(const float* __restrict__ bias,
                       float* __restrict__ out) {
    const int wid  = (int)((blockIdx.x * (size_t)blockDim.x + threadIdx.x) >> 5);
    const int lane = threadIdx.x & 31;
    const unsigned FULL = 0xffffffffu;

    const int n0 = wid * 2;
    const int n1 = n0 + 1;
    if (n0 >= N_NODES) return;
    const bool has1 = (n1 < N_NODES);

    int cnt0 = g_cnt[n0]; if (cnt0 > DEG_CAP) cnt0 = DEG_CAP;
    int cnt1 = 0;
    if (has1) { cnt1 = g_cnt[n1]; if (cnt1 > DEG_CAP) cnt1 = DEG_CAP; }

    const int sidx0 = g_bin[(size_t)n0 * DEG_CAP + lane];
    const int sidx1 = has1 ? g_bin[(size_t)n1 * DEG_CAP + lane] : 0;
    const uint2* y2 = reinterpret_cast<const uint2*>(g_y) + lane;   // row stride 32

    float a0 = 0.f, a1 = 0.f, a2 = 0.f, a3 = 0.f;   // node n0
    float c0 = 0.f, c1 = 0.f, c2 = 0.f, c3 = 0.f;   // node n1

    const int nb0 = (cnt0 < 32) ? cnt0 : 32;
    const int nb1 = (cnt1 < 32) ? cnt1 : 32;
    const int nbmin = (nb0 < nb1) ? nb0 : nb1;

    // ---- Common phase: dual 8-edge batches, 16 loads in flight ----
    int e = 0;
    for (; e + 8 <= nbmin; e += 8) {
        uint2 u[8], v[8];
        #pragma unroll
        for (int j = 0; j < 8; j++) {
            int s = __shfl_sync(FULL, sidx0, e + j);
            u[j] = y2[(size_t)s * 32];
        }
        #pragma unroll
        for (int j = 0; j < 8; j++) {
            int s = __shfl_sync(FULL, sidx1, e + j);
            v[j] = y2[(size_t)s * 32];
        }
        #pragma unroll
        for (int j = 0; j < 8; j += 2) {
            __half2 ha = __hadd2(as_h2(u[j].x), as_h2(u[j + 1].x));
            __half2 hb = __hadd2(as_h2(u[j].y), as_h2(u[j + 1].y));
            float2 fa = __half22float2(ha);
            float2 fb = __half22float2(hb);
            a0 += fa.x; a1 += fa.y; a2 += fb.x; a3 += fb.y;
            __half2 hc = __hadd2(as_h2(v[j].x), as_h2(v[j + 1].x));
            __half2 hd = __hadd2(as_h2(v[j].y), as_h2(v[j + 1].y));
            float2 fc = __half22float2(hc);
            float2 fd = __half22float2(hd);
            c0 += fc.x; c1 += fc.y; c2 += fd.x; c3 += fd.y;
        }
    }

    // ---- Tails per node ----
    int e0 = e;
    for (; e0 + 8 <= nb0; e0 += 8) batch8(y2, sidx0, e0, a0, a1, a2, a3);
    for (; e0 < nb0; e0++)         edge1(y2, sidx0, e0, a0, a1, a2, a3);
    int e1 = e;
    for (; e1 + 8 <= nb1; e1 += 8) batch8(y2, sidx1, e1, c0, c1, c2, c3);
    for (; e1 < nb1; e1++)         edge1(y2, sidx1, e1, c0, c1, c2, c3);

    // ---- rare: degree > 32 (base+lane <= 95 < DEG_CAP: load in-bounds) ----
    for (int base = 32; base < cnt0; base += 32) {
        int sx = g_bin[(size_t)n0 * DEG_CAP + base + lane];
        int nb2 = cnt0 - base; if (nb2 > 32) nb2 = 32;
        for (int t = 0; t < nb2; t++) edge1(y2, sx, t, a0, a1, a2, a3);
    }
    for (int base = 32; base < cnt1; base += 32) {
        int sx = g_bin[(size_t)n1 * DEG_CAP + base + lane];
        int nb2 = cnt1 - base; if (nb2 > 32) nb2 = 32;
        for (int t = 0; t < nb2; t++) edge1(y2, sx, t, c0, c1, c2, c3);
    }

    // ---- bias + relu; lane covers cols 4l..4l+3 ----
    float4 bv = *reinterpret_cast<const float4*>(bias + 4 * lane);
    {
        float4 o;
        o.x = fmaxf(a0 + bv.x, 0.f);
        o.y = fmaxf(a1 + bv.y, 0.f);
        o.z = fmaxf(a2 + bv.z, 0.f);
        o.w = fmaxf(a3 + bv.w, 0.f);
        *reinterpret_cast<float4*>(out + (size_t)n0 * NFEAT + 4 * lane) = o;
    }
    if (has1) {
        float4 o;
        o.x = fmaxf(c0 + bv.x, 0.f);
        o.y = fmaxf(c1 + bv.y, 0.f);
        o.z = fmaxf(c2 + bv.z, 0.f);
        o.w = fmaxf(c3 + bv.w, 0.f);
        *reinterpret_cast<float4*>(out + (size_t)n1 * NFEAT + 4 * lane) = o;
    }

    // restore invariant for next replay
    if (lane == 0) g_cnt[n0] = 0;
    if (lane == 1 && has1) g_cnt[n1] = 0;
}

// ---------------------------------------------------------------------------
// kernel_launch
// Inputs: feature [N,128] f32, src_idx [E] i32, dst_idx [E] i32,
//         W [128,128] f32, b [128] f32.  Output: [N,128] f32.
// 4 launches: splitw, fill, matmul, gather (capture slot index 3 = gather).
// ---------------------------------------------------------------------------
extern "C" void kernel_launch(void* const* d_in, const int* in_sizes, int n_in,
                              void* d_out, int out_size) {
    const float* feature = (const float*)d_in[0];
    const int*   src_idx = (const int*)d_in[1];
    const int*   dst_idx = (const int*)d_in[2];
    const float* Wm      = (const float*)d_in[3];
    const float* bias    = (const float*)d_in[4];
    float*       out     = (float*)d_out;

    const int SMEM_GEMM = (2 * BM * ASU + 2 * 128 * WSU) * 4;  // 71680 B
    cudaFuncSetAttribute(matmul_kernel,
                         cudaFuncAttributeMaxDynamicSharedMemorySize, SMEM_GEMM);

    // 1) W bf16 split
    splitw_kernel<<<32, 256>>>(Wm);

    // 2) binned edge fill (one edge per thread)
    fill_kernel<<<(N_EDGES + 255) / 256, 256>>>(src_idx, dst_idx);

    // 3) Y = F @ W^T (bf16 3-pass tensor cores, fp16 output)
    int gemm_blocks = (N_NODES + BM - 1) / BM;        // 782
    matmul_kernel<<<gemm_blocks, 256, SMEM_GEMM>>>(feature);

    // 4) gather + bias + relu (two nodes per warp, dual edge streams)
    int warps = (N_NODES + 1) / 2;                    // 25000
    int gather_blocks = (warps * 32 + 255) / 256;     // 3125
    gather_out_kernel<<<gather_blocks, 256>>>(bias, out);
}